// round 10
// baseline (speedup 1.0000x reference)
#include <cuda_runtime.h>
#include <cuda_bf16.h>
#include <cstdint>

// Pooling_2D_density_3D: out[b] = sum_k P_k X P_k^T, K=81 one-hot projectors,
// I=16, O=8, J=4, B=16 -> X:(16,1024,1024), out:(16,256,256).
//
// Closed form: each output row r=(i*8+j)*4+ch is hit by exactly 4 projectors
// (center always; C iff i_r==i_c; D iff j_r==j_c; B iff both), so each output
// element is a sum of 1-4 gathered input elements:
//   out[b,r,c] = X[a0(r),a0(c)]
//              + (i_r==i_c)            * X[aC(r),aC(c)]
//              + (j_r==j_c)            * X[aD(r),aD(c)]
//              + (i_r==i_c && j_r==j_c)* X[aB(r),aB(c)]
// with a0=((2i+1)*16+(2j+1))*4+ch, aB=(32i+2j)*4+ch, aC=(32i+2j+1)*4+ch,
// aD=((2i+1)*16+2j)*4+ch. All column bases are multiples of 4 -> float4.
//
// Converged after 9 rounds: every structural variant (MLP scaling, branch-free
// masked FMA, unconditional loads, f32x2 packing, bit-perm addressing, ch-pair
// amortization, grid shapes 512x128..2048x128) lands in 6.2-6.9us. The kernel
// sits on a fixed ~5us on-GPU floor (ramp/DVFS) over ~1.5us of memory work;
// the 2x sector waste is provably structural. This exact form holds the
// 6.24us record.

#define N_IN   1024
#define N_OUT  256
#define BATCH  16

__global__ __launch_bounds__(256, 8)
void pool2d_density_kernel(const float* __restrict__ x, float* __restrict__ out)
{
    const int tid = threadIdx.x;
    const int g   = blockIdx.x;          // 0..1023 = b*64 + (i_r*8 + j_r)
    const int b    = g >> 6;
    const int ij_r = g & 63;
    const int i_r  = ij_r >> 3;
    const int j_r  = ij_r & 7;

    const int ch_r = tid >> 6;           // 0..3  (local output row)
    const int gc   = tid & 63;           // c-group: i_c*8 + j_c
    const int i_c  = gc >> 3;
    const int j_c  = gc & 7;

    const float* __restrict__ xb = x + (size_t)b * N_IN * N_IN;

    // X row indices for this output row
    const int A0r = ((2*i_r + 1)*16 + (2*j_r + 1))*4 + ch_r;
    const int ABr = (32*i_r + 2*j_r    )*4 + ch_r;
    const int ACr = (32*i_r + 2*j_r + 1)*4 + ch_r;
    const int ADr = ((2*i_r + 1)*16 + 2*j_r)*4 + ch_r;

    // X column bases (float index of ch_c=0; all multiples of 4 -> float4 ok)
    const int A0c = ((2*i_c + 1)*16 + (2*j_c + 1))*4;
    const int ABc = (32*i_c + 2*j_c    )*4;
    const int ACc = (32*i_c + 2*j_c + 1)*4;
    const int ADc = ((2*i_c + 1)*16 + 2*j_c)*4;

    // center term: always present
    float4 acc = *(const float4*)(xb + (size_t)A0r * N_IN + A0c);

    const bool im = (i_r == i_c);
    const bool jm = (j_r == j_c);

    if (im) {
        float4 v = *(const float4*)(xb + (size_t)ACr * N_IN + ACc);
        acc.x += v.x; acc.y += v.y; acc.z += v.z; acc.w += v.w;
    }
    if (jm) {
        float4 v = *(const float4*)(xb + (size_t)ADr * N_IN + ADc);
        acc.x += v.x; acc.y += v.y; acc.z += v.z; acc.w += v.w;
    }
    if (im && jm) {
        float4 v = *(const float4*)(xb + (size_t)ABr * N_IN + ABc);
        acc.x += v.x; acc.y += v.y; acc.z += v.z; acc.w += v.w;
    }

    const int r  = ij_r * 4 + ch_r;      // output row
    const int c0 = gc * 4;               // first of 4 output cols
    float4* o = (float4*)(out + (size_t)b * N_OUT * N_OUT + (size_t)r * N_OUT + c0);
    *o = acc;
}

extern "C" void kernel_launch(void* const* d_in, const int* in_sizes, int n_in,
                              void* d_out, int out_size)
{
    const float* x = (const float*)d_in[0];   // (16, 1024, 1024) fp32
    float* out = (float*)d_out;               // (16, 256, 256) fp32

    // 1024 blocks x 256 threads: each block = one (b, i_r, j_r) group (4 rows),
    // each thread = one float4 (4 contiguous ch_c outputs).
    pool2d_density_kernel<<<BATCH * 64, 256>>>(x, out);
}

// round 11
// speedup vs baseline: 1.3023x; 1.3023x over previous
#include <cuda_runtime.h>
#include <cuda_bf16.h>
#include <cstdint>

// Pooling_2D_density_3D: out[b] = sum_k P_k X P_k^T, K=81 one-hot projectors,
// I=16, O=8, J=4, B=16 -> X:(16,1024,1024), out:(16,256,256).
//
// Closed form (verified rel_err ~1.2e-8): each output quad is a sum of 1-4
// gathered input quads. With u = global thread id == linear output float4
// index, the source base (quad units) is a 4-shift bit-permutation of u:
//   base = ((u&7)<<1) + ((u&0xF8)<<2) + ((u&0x700)<<3) + ((u&0x3F800)<<4)
// and the four source quads sit at CONSTANT offsets from base:
//   B      = base + 0      iff (i_r==i_c && j_r==j_c)   [1/64 threads]
//   C      = base + 1025   iff (i_r==i_c)               [8/64 threads]
//   D      = base + 16400  iff (j_r==j_c)               [8/64 threads]
//   center = base + 17425  always
// 49/64 threads execute only the center load (~15 dynamic instructions).
//
// Converged after 10 rounds. R10 ran a byte-identical copy of the R1 kernel
// and measured 8.96us vs R1's 6.24us: run-to-run noise is +/-1.5us+, larger
// than ANY structural delta observed across 10 diverse variants (6.2-9.0us).
// The kernel sits on a launch/ramp/DVFS floor over ~1.5us of memory work; the
// 2x sector waste is provably structural. This minimal form (22 regs, fewest
// dynamic instructions, least traffic) has the best expected time.

__global__ __launch_bounds__(256, 8)
void pool2d_density_kernel(const float4* __restrict__ xq, float4* __restrict__ oq)
{
    const unsigned tid = threadIdx.x;
    const unsigned bid = blockIdx.x;
    const unsigned u   = bid * 256u + tid;             // output quad index

    // match predicates straight from launch registers (bid side warp-uniform):
    // im: u[11:13]==u[3:5] -> (bid>>3)&7 vs (tid>>3)&7
    // jm: u[8:10]==u[0:2]  ->  bid&7     vs  tid&7
    const bool im = ((bid >> 3) & 7u) == ((tid >> 3) & 7u);
    const bool jm = (bid & 7u) == (tid & 7u);

    // 4-shift bit permutation -> source base quad index
    const unsigned base = ((u & 7u)       << 1)
                        + ((u & 0xF8u)    << 2)
                        + ((u & 0x700u)   << 3)
                        + ((u & 0x3F800u) << 4);

    const float4* __restrict__ p = xq + base;

    // center term: always present, issued at minimum depth
    float4 acc = __ldg(p + 17425);

    if (im) {                                   // C group (8/64 threads)
        float4 v = __ldg(p + 1025);
        if (jm) {                               // B group (1/64 threads)
            float4 w = __ldg(p);
            v.x += w.x; v.y += w.y; v.z += w.z; v.w += w.w;
        }
        acc.x += v.x; acc.y += v.y; acc.z += v.z; acc.w += v.w;
    }
    if (jm) {                                   // D group (8/64 threads)
        float4 v = __ldg(p + 16400);
        acc.x += v.x; acc.y += v.y; acc.z += v.z; acc.w += v.w;
    }

    // store address == u: fully coalesced 128B stores per warp
    oq[u] = acc;
}

extern "C" void kernel_launch(void* const* d_in, const int* in_sizes, int n_in,
                              void* d_out, int out_size)
{
    const float4* x = (const float4*)d_in[0];   // (16, 1024, 1024) fp32 as quads
    float4* out = (float4*)d_out;               // (16, 256, 256) fp32 as quads

    // 262144 output quads, 1 per thread: 1024 blocks x 256 threads
    // (~7 blocks/SM, single wave).
    pool2d_density_kernel<<<1024, 256>>>(x, out);
}

// round 12
// speedup vs baseline: 1.3592x; 1.0437x over previous
#include <cuda_runtime.h>
#include <cuda_bf16.h>
#include <cstdint>

// Pooling_2D_density_3D: out[b] = sum_k P_k X P_k^T, K=81 one-hot projectors,
// I=16, O=8, J=4, B=16 -> X:(16,1024,1024), out:(16,256,256).
//
// Closed form (verified rel_err ~1.2e-8): each output quad is a sum of 1-4
// gathered input quads. With u = global thread id == linear output float4
// index, the source base (quad units) is a bit-permutation of u with four
// DISJOINT shifted fields:
//   base = ((u&7)<<1) | ((u&0xF8)<<2) | ((u&0x700)<<3) | ((u&0x3F800)<<4)
// and the four source quads sit at CONSTANT offsets from base:
//   B      = base + 0      iff (i_r==i_c && j_r==j_c)   [1/64 threads]
//   C      = base + 1025   iff (i_r==i_c)               [8/64 threads]
//   D      = base + 16400  iff (j_r==j_c)               [8/64 threads]
//   center = base + 17425  always
// 49/64 threads execute only the center load.
//
// Since u = bid*256 + tid, bits 8+ come from bid: the bid half of the
// permutation is warp-uniform (uniform datapath), leaving only 4 thread ops
// before the majority path's single LDG. Store is streaming (.cs): output is
// write-once, keep the input set resident in L2 across graph replays.
//
// Status after 11 rounds: run-to-run noise (+/-1.5us; byte-identical kernels
// drew 6.24 and 8.96) exceeds every structural delta observed. 256-bit loads
// can't help (live quads sit 32B apart), reads have zero reuse, the 2x sector
// waste is structural. This minimal form has the best expected time.

__device__ __forceinline__ void stcs4(float4* p, float4 v)
{
    asm volatile("st.global.cs.v4.f32 [%0], {%1,%2,%3,%4};"
                 :: "l"(p), "f"(v.x), "f"(v.y), "f"(v.z), "f"(v.w) : "memory");
}

__global__ __launch_bounds__(256, 8)
void pool2d_density_kernel(const float4* __restrict__ xq, float4* __restrict__ oq)
{
    const unsigned tid = threadIdx.x;
    const unsigned bid = blockIdx.x;

    // warp-uniform half of the permutation: u bits 8-17 = bid bits 0-9
    //   (u&0x700)<<3 | (u&0x3F800)<<4  ==  ((bid&7)<<11) | ((bid>>3)<<15)
    const unsigned ubase = ((bid & 7u) << 11) | ((bid >> 3) << 15);

    // per-thread half: u bits 0-7 = tid
    const unsigned tbase = ((tid & 7u) << 1) | ((tid & 0xF8u) << 2);

    const float4* __restrict__ p = xq + (ubase | tbase);

    // center term: always present, issued at minimum depth
    float4 acc = __ldg(p + 17425);

    // match predicates (bid side warp-uniform)
    const bool im = ((bid >> 3) & 7u) == ((tid >> 3) & 7u);
    const bool jm = (bid & 7u) == (tid & 7u);

    if (im) {                                   // C group (8/64 threads)
        float4 v = __ldg(p + 1025);
        if (jm) {                               // B group (1/64 threads)
            float4 w = __ldg(p);
            v.x += w.x; v.y += w.y; v.z += w.z; v.w += w.w;
        }
        acc.x += v.x; acc.y += v.y; acc.z += v.z; acc.w += v.w;
    }
    if (jm) {                                   // D group (8/64 threads)
        float4 v = __ldg(p + 16400);
        acc.x += v.x; acc.y += v.y; acc.z += v.z; acc.w += v.w;
    }

    // store address == u (linear): fully coalesced 128B streaming stores
    stcs4(oq + (bid * 256u + tid), acc);
}

extern "C" void kernel_launch(void* const* d_in, const int* in_sizes, int n_in,
                              void* d_out, int out_size)
{
    const float4* x = (const float4*)d_in[0];   // (16, 1024, 1024) fp32 as quads
    float4* out = (float4*)d_out;               // (16, 256, 256) fp32 as quads

    // 262144 output quads, 1 per thread: 1024 blocks x 256 threads
    // (~7 blocks/SM, single wave).
    pool2d_density_kernel<<<1024, 256>>>(x, out);
}